// round 3
// baseline (speedup 1.0000x reference)
#include <cuda_runtime.h>
#include <cstdint>

// Problem constants
#define ROWS  65536      // B*N rows
#define NPTS  16384      // N
#define EPB   131072     // E per batch (N*K)
#define KNN   8

// ---------------- scratch (device globals; no allocation allowed) ----------
__device__ float g_x0[ROWS * 32];
__device__ float g_x1[ROWS * 64];
__device__ float g_x2[ROWS * 128];
__device__ float g_x3[ROWS * 256];
__device__ float g_za[ROWS * 256];
__device__ float g_zb[ROWS * 256];
__device__ float g_zc[ROWS];
__device__ float g_pa[256 * 256 * 2];   // stage-1 partials (branch a)
__device__ float g_pb[256 * 256 * 2];   // stage-1 partials (branch b)
__device__ float g_sa[256], g_ha[256];  // BN scale/shift branch a
__device__ float g_sb[256], g_hb[256];  // BN scale/shift branch b

// ---------------- f32x2 helpers --------------------------------------------
__device__ __forceinline__ unsigned long long pack_dup(float a) {
    unsigned long long r;
    unsigned int ab = __float_as_uint(a);
    asm("mov.b64 %0, {%1, %1};" : "=l"(r) : "r"(ab));
    return r;
}

// ---------------- GEMM: C[ROWS,COUT] = A[ROWS,CIN] @ W[CIN,COUT] ------------
template <int CIN, int COUT>
__global__ void __launch_bounds__(256) gemm_k(const float* __restrict__ A,
                                              const float* __restrict__ W,
                                              float* __restrict__ C) {
    constexpr int BM = 128;
    constexpr int BN = (COUT < 128) ? COUT : 128;
    constexpr int TM = 8;
    constexpr int TN = BN / 16;           // 2, 4, or 8
    constexpr int BK = 8;

    __shared__ float As[BM * BK];         // [BM][BK] row-major
    __shared__ float Ws[BK * BN];         // [BK][BN]

    const int t   = threadIdx.x;
    const int tx  = t & 15;
    const int ty  = t >> 4;
    const int row0 = blockIdx.x * BM;
    const int col0 = blockIdx.y * BN;

    unsigned long long acc[TM][TN / 2];
#pragma unroll
    for (int m = 0; m < TM; m++)
#pragma unroll
        for (int j = 0; j < TN / 2; j++) acc[m][j] = 0ULL;

    for (int k0 = 0; k0 < CIN; k0 += BK) {
        // Load A tile (coalesced along K within each row)
#pragma unroll
        for (int idx = t; idx < BM * BK; idx += 256) {
            int r = idx >> 3, c = idx & 7;
            As[r * BK + c] = A[(row0 + r) * CIN + k0 + c];
        }
        // Load W tile (coalesced along COUT)
#pragma unroll
        for (int idx = t; idx < BK * BN; idx += 256) {
            int kr = idx / BN, c = idx % BN;
            Ws[kr * BN + c] = W[(k0 + kr) * COUT + col0 + c];
        }
        __syncthreads();

#pragma unroll
        for (int k = 0; k < BK; k++) {
            unsigned long long a2[TM];
#pragma unroll
            for (int m = 0; m < TM; m++)
                a2[m] = pack_dup(As[(ty * TM + m) * BK + k]);
            unsigned long long w2[TN / 2];
#pragma unroll
            for (int j = 0; j < TN / 2; j++)
                w2[j] = *reinterpret_cast<const unsigned long long*>(
                    &Ws[k * BN + tx * TN + 2 * j]);
#pragma unroll
            for (int m = 0; m < TM; m++)
#pragma unroll
                for (int j = 0; j < TN / 2; j++)
                    asm("fma.rn.f32x2 %0, %1, %2, %0;"
                        : "+l"(acc[m][j]) : "l"(a2[m]), "l"(w2[j]));
        }
        __syncthreads();
    }

#pragma unroll
    for (int m = 0; m < TM; m++) {
        int r = row0 + ty * TM + m;
#pragma unroll
        for (int j = 0; j < TN / 2; j++)
            *reinterpret_cast<unsigned long long*>(
                &C[r * COUT + col0 + tx * TN + 2 * j]) = acc[m][j];
    }
}

// ---------------- BN stats, stage 1 (node-level buffers) --------------------
// grid=256 blocks (256 rows each), block=256 threads. Deterministic.
__global__ void __launch_bounds__(256) stats1_k(const float* __restrict__ z,
                                                int cout,
                                                float* __restrict__ part) {
    __shared__ float sh[512];
    const int t = threadIdx.x, blk = blockIdx.x;
    const int ng  = 256 / cout;
    const int ch  = t & (cout - 1);
    const int grp = t / cout;
    const int row0 = blk * 256;
    float s = 0.f, s2 = 0.f;
    for (int r = grp; r < 256; r += ng) {
        float v = z[(row0 + r) * cout + ch];
        s += v; s2 += v * v;
    }
    sh[t] = s; sh[256 + t] = s2;
    __syncthreads();
    if (t < cout) {
        float a = 0.f, b = 0.f;
        for (int g = 0; g < ng; g++) { a += sh[g * cout + t]; b += sh[256 + g * cout + t]; }
        part[blk * cout * 2 + t]        = a;
        part[blk * cout * 2 + cout + t] = b;
    }
}

// ---------------- BN stats, stage 2: sum partials -> scale/shift ------------
__global__ void stats2_k(const float* __restrict__ part,
                         const float* __restrict__ gam,
                         const float* __restrict__ bet,
                         int cout, float invM,
                         float* __restrict__ scale, float* __restrict__ shift) {
    int t = threadIdx.x;
    if (t >= cout) return;
    float s = 0.f, s2 = 0.f;
    for (int blk = 0; blk < 256; blk++) {
        s  += part[blk * cout * 2 + t];
        s2 += part[blk * cout * 2 + cout + t];
    }
    float m = s * invM;
    float v = fmaxf(s2 * invM - m * m, 0.f);
    float sc = gam[t] * rsqrtf(v + 1e-5f);
    scale[t] = sc;
    shift[t] = bet[t] - m * sc;
}

// ---------------- edge-level stats for layer-0 branch b ---------------------
// d_e = zb[nbr_e] - zb[ctr_e] over 524288 edges, 32 channels.
__global__ void __launch_bounds__(256) estats1_k(const float* __restrict__ zb,
                                                 const int* __restrict__ ei,
                                                 float* __restrict__ part) {
    __shared__ float sh[512];
    const int t = threadIdx.x, blk = blockIdx.x;
    const int ch = t & 31, grp = t >> 5;   // 8 groups of one warp each
    const int e0 = blk * 2048;
    float s = 0.f, s2 = 0.f;
    for (int i = grp; i < 2048; i += 8) {
        int ge  = e0 + i;
        int b   = ge >> 17;               // /EPB
        int e   = ge & (EPB - 1);
        int ctr = (b << 14) + (e >> 3);   // centers = repeat(arange(N),K)
        int nbr = (b << 14) + ei[b * 2 * EPB + EPB + e];
        float d = zb[nbr * 32 + ch] - zb[ctr * 32 + ch];
        s += d; s2 += d * d;
    }
    sh[t] = s; sh[256 + t] = s2;
    __syncthreads();
    if (t < 32) {
        float a = 0.f, b2 = 0.f;
        for (int g = 0; g < 8; g++) { a += sh[g * 32 + t]; b2 += sh[256 + g * 32 + t]; }
        part[blk * 64 + t]      = a;
        part[blk * 64 + 32 + t] = b2;
    }
}

// ---------------- combine: x_out = act_a(za) + max_k act_b(zb[nbr_k](-zb)) --
__global__ void __launch_bounds__(256) combine_k(const float* __restrict__ za,
                                                 const float* __restrict__ zb,
                                                 const int* __restrict__ ei,
                                                 float* __restrict__ xo,
                                                 int cout, int diffMode) {
    const int t = threadIdx.x;
    const int npb  = 256 / cout;
    const int node = blockIdx.x * npb + t / cout;
    const int ch   = t & (cout - 1);
    const int b = node >> 14, n = node & (NPTS - 1);
    const int* nb = ei + b * 2 * EPB + EPB + n * KNN;
    const int boff = b << 14;

    const float sb = g_sb[ch], hb = g_hb[ch];
    const float zc = diffMode ? zb[node * cout + ch] : 0.f;
    float mx = -1e30f;
#pragma unroll
    for (int k = 0; k < KNN; k++) {
        int nn = boff + nb[k];
        float v = (zb[nn * cout + ch] - zc) * sb + hb;
        v = v > 0.f ? v : 0.2f * v;
        mx = fmaxf(mx, v);
    }
    float va = za[node * cout + ch] * g_sa[ch] + g_ha[ch];
    va = va > 0.f ? va : 0.2f * va;
    xo[node * cout + ch] = va + mx;
}

// ---------------- cat projection: zc[row] = concat(x0..x3)[row] . Wcat ------
__global__ void __launch_bounds__(256) cat_k(const float* __restrict__ Wc) {
    const int warp = threadIdx.x >> 5, lane = threadIdx.x & 31;
    const int row = blockIdx.x * 8 + warp;
    float s = 0.f;
#pragma unroll
    for (int i = 0; i < 15; i++) {        // 480 / 32
        int j = lane + i * 32;
        float v;
        if (j < 32)       v = g_x0[row * 32  + j];
        else if (j < 96)  v = g_x1[row * 64  + (j - 32)];
        else if (j < 224) v = g_x2[row * 128 + (j - 96)];
        else              v = g_x3[row * 256 + (j - 224)];
        s += v * Wc[j];
    }
#pragma unroll
    for (int o = 16; o; o >>= 1) s += __shfl_xor_sync(0xffffffffu, s, o);
    if (lane == 0) g_zc[row] = s;
}

// ---------------- final: BN(1ch) + lrelu + bias -----------------------------
__global__ void final_k(const float* __restrict__ bias, float* __restrict__ out) {
    int i = blockIdx.x * 256 + threadIdx.x;
    float v = g_zc[i] * g_sa[0] + g_ha[0];
    v = v > 0.f ? v : 0.2f * v;
    out[i] = v + bias[0];
}

// ---------------- host orchestration ----------------------------------------
extern "C" void kernel_launch(void* const* d_in, const int* in_sizes, int n_in,
                              void* d_out, int out_size) {
    const float* x   = (const float*)d_in[0];
    const int*   ei  = (const int*)d_in[1];
    const float* W0a = (const float*)d_in[2];
    const float* g0a = (const float*)d_in[3];
    const float* b0a = (const float*)d_in[4];
    const float* W0b = (const float*)d_in[5];
    const float* g0b = (const float*)d_in[6];
    const float* b0b = (const float*)d_in[7];
    const float* W1a = (const float*)d_in[8];
    const float* g1a = (const float*)d_in[9];
    const float* b1a = (const float*)d_in[10];
    const float* W1b = (const float*)d_in[11];
    const float* g1b = (const float*)d_in[12];
    const float* b1b = (const float*)d_in[13];
    const float* W2a = (const float*)d_in[14];
    const float* g2a = (const float*)d_in[15];
    const float* b2a = (const float*)d_in[16];
    const float* W2b = (const float*)d_in[17];
    const float* g2b = (const float*)d_in[18];
    const float* b2b = (const float*)d_in[19];
    const float* W3a = (const float*)d_in[20];
    const float* g3a = (const float*)d_in[21];
    const float* b3a = (const float*)d_in[22];
    const float* W3b = (const float*)d_in[23];
    const float* g3b = (const float*)d_in[24];
    const float* b3b = (const float*)d_in[25];
    const float* Wct = (const float*)d_in[26];
    const float* gct = (const float*)d_in[27];
    const float* bct = (const float*)d_in[28];
    const float* bia = (const float*)d_in[29];
    float* out = (float*)d_out;

    float *x0, *x1, *x2, *x3, *za, *zb, *zc, *pa, *pb, *sa, *ha, *sb, *hb;
    cudaGetSymbolAddress((void**)&x0, g_x0);
    cudaGetSymbolAddress((void**)&x1, g_x1);
    cudaGetSymbolAddress((void**)&x2, g_x2);
    cudaGetSymbolAddress((void**)&x3, g_x3);
    cudaGetSymbolAddress((void**)&za, g_za);
    cudaGetSymbolAddress((void**)&zb, g_zb);
    cudaGetSymbolAddress((void**)&zc, g_zc);
    cudaGetSymbolAddress((void**)&pa, g_pa);
    cudaGetSymbolAddress((void**)&pb, g_pb);
    cudaGetSymbolAddress((void**)&sa, g_sa);
    cudaGetSymbolAddress((void**)&ha, g_ha);
    cudaGetSymbolAddress((void**)&sb, g_sb);
    cudaGetSymbolAddress((void**)&hb, g_hb);

    const float invN = 1.0f / 65536.0f;
    const float invE = 1.0f / 524288.0f;

    // ---- layer 0: 8 -> 32 ----
    gemm_k<8, 32><<<dim3(ROWS / 128, 1), 256>>>(x, W0a, za);
    gemm_k<8, 32><<<dim3(ROWS / 128, 1), 256>>>(x, W0b, zb);
    stats1_k<<<256, 256>>>(za, 32, pa);
    stats2_k<<<1, 256>>>(pa, g0a, b0a, 32, invN, sa, ha);
    estats1_k<<<256, 256>>>(zb, ei, pb);
    stats2_k<<<1, 256>>>(pb, g0b, b0b, 32, invE, sb, hb);
    combine_k<<<ROWS * 32 / 256, 256>>>(za, zb, ei, x0, 32, 1);

    // ---- layer 1: 32 -> 64 ----
    gemm_k<32, 64><<<dim3(ROWS / 128, 1), 256>>>(x0, W1a, za);
    gemm_k<32, 64><<<dim3(ROWS / 128, 1), 256>>>(x0, W1b, zb);
    stats1_k<<<256, 256>>>(za, 64, pa);
    stats2_k<<<1, 256>>>(pa, g1a, b1a, 64, invN, sa, ha);
    stats1_k<<<256, 256>>>(zb, 64, pb);
    stats2_k<<<1, 256>>>(pb, g1b, b1b, 64, invN, sb, hb);
    combine_k<<<ROWS * 64 / 256, 256>>>(za, zb, ei, x1, 64, 0);

    // ---- layer 2: 64 -> 128 ----
    gemm_k<64, 128><<<dim3(ROWS / 128, 1), 256>>>(x1, W2a, za);
    gemm_k<64, 128><<<dim3(ROWS / 128, 1), 256>>>(x1, W2b, zb);
    stats1_k<<<256, 256>>>(za, 128, pa);
    stats2_k<<<1, 256>>>(pa, g2a, b2a, 128, invN, sa, ha);
    stats1_k<<<256, 256>>>(zb, 128, pb);
    stats2_k<<<1, 256>>>(pb, g2b, b2b, 128, invN, sb, hb);
    combine_k<<<ROWS * 128 / 256, 256>>>(za, zb, ei, x2, 128, 0);

    // ---- layer 3: 128 -> 256 ----
    gemm_k<128, 256><<<dim3(ROWS / 128, 2), 256>>>(x2, W3a, za);
    gemm_k<128, 256><<<dim3(ROWS / 128, 2), 256>>>(x2, W3b, zb);
    stats1_k<<<256, 256>>>(za, 256, pa);
    stats2_k<<<1, 256>>>(pa, g3a, b3a, 256, invN, sa, ha);
    stats1_k<<<256, 256>>>(zb, 256, pb);
    stats2_k<<<1, 256>>>(pb, g3b, b3b, 256, invN, sb, hb);
    combine_k<<<ROWS * 256 / 256, 256>>>(za, zb, ei, x3, 256, 0);

    // ---- cat 480 -> 1, BN, lrelu, +bias ----
    cat_k<<<ROWS / 8, 256>>>(Wct);
    stats1_k<<<256, 256>>>(zc, 1, pa);
    stats2_k<<<1, 256>>>(pa, gct, bct, 1, invN, sa, ha);
    final_k<<<ROWS / 256, 256>>>(bia, out);
}

// round 5
// speedup vs baseline: 1.0004x; 1.0004x over previous
#include <cuda_runtime.h>
#include <cstdint>

// Problem constants
#define ROWS  65536      // B*N rows
#define NPTS  16384      // N
#define EPB   131072     // E per batch (N*K)
#define KNN   8

// ---------------- scratch (device globals; no allocation allowed) ----------
__device__ float g_x0[ROWS * 32];
__device__ float g_x1[ROWS * 64];
__device__ float g_x2[ROWS * 128];
__device__ float g_x3[ROWS * 256];
__device__ float g_za[ROWS * 256];
__device__ float g_zb[ROWS * 256];
__device__ float g_zc[ROWS];
__device__ float g_pa[256 * 256 * 2];   // stage-1 partials (branch a)
__device__ float g_pb[256 * 256 * 2];   // stage-1 partials (branch b)
__device__ float g_sa[256], g_ha[256];  // BN scale/shift branch a
__device__ float g_sb[256], g_hb[256];  // BN scale/shift branch b

// ---------------- f32x2 helpers --------------------------------------------
__device__ __forceinline__ unsigned long long pack_dup(float a) {
    unsigned long long r;
    unsigned int ab = __float_as_uint(a);
    asm("mov.b64 %0, {%1, %1};" : "=l"(r) : "r"(ab));
    return r;
}

// ---------------- GEMM: C[ROWS,COUT] = A[ROWS,CIN] @ W[CIN,COUT] ------------
template <int CIN, int COUT>
__global__ void __launch_bounds__(256) gemm_k(const float* __restrict__ A,
                                              const float* __restrict__ W,
                                              float* __restrict__ C) {
    constexpr int BM = 128;
    constexpr int BN = (COUT < 128) ? COUT : 128;
    constexpr int TM = 8;
    constexpr int TN = BN / 16;           // 2, 4, or 8
    constexpr int BK = 8;

    __shared__ float As[BM * BK];         // [BM][BK] row-major
    __shared__ float Ws[BK * BN];         // [BK][BN]

    const int t   = threadIdx.x;
    const int tx  = t & 15;
    const int ty  = t >> 4;
    const int row0 = blockIdx.x * BM;
    const int col0 = blockIdx.y * BN;

    unsigned long long acc[TM][TN / 2];
#pragma unroll
    for (int m = 0; m < TM; m++)
#pragma unroll
        for (int j = 0; j < TN / 2; j++) acc[m][j] = 0ULL;

    for (int k0 = 0; k0 < CIN; k0 += BK) {
        // Load A tile (coalesced along K within each row)
#pragma unroll
        for (int idx = t; idx < BM * BK; idx += 256) {
            int r = idx >> 3, c = idx & 7;
            As[r * BK + c] = A[(row0 + r) * CIN + k0 + c];
        }
        // Load W tile (coalesced along COUT)
#pragma unroll
        for (int idx = t; idx < BK * BN; idx += 256) {
            int kr = idx / BN, c = idx % BN;
            Ws[kr * BN + c] = W[(k0 + kr) * COUT + col0 + c];
        }
        __syncthreads();

#pragma unroll
        for (int k = 0; k < BK; k++) {
            unsigned long long a2[TM];
#pragma unroll
            for (int m = 0; m < TM; m++)
                a2[m] = pack_dup(As[(ty * TM + m) * BK + k]);
            unsigned long long w2[TN / 2];
#pragma unroll
            for (int j = 0; j < TN / 2; j++)
                w2[j] = *reinterpret_cast<const unsigned long long*>(
                    &Ws[k * BN + tx * TN + 2 * j]);
#pragma unroll
            for (int m = 0; m < TM; m++)
#pragma unroll
                for (int j = 0; j < TN / 2; j++)
                    asm("fma.rn.f32x2 %0, %1, %2, %0;"
                        : "+l"(acc[m][j]) : "l"(a2[m]), "l"(w2[j]));
        }
        __syncthreads();
    }

#pragma unroll
    for (int m = 0; m < TM; m++) {
        int r = row0 + ty * TM + m;
#pragma unroll
        for (int j = 0; j < TN / 2; j++)
            *reinterpret_cast<unsigned long long*>(
                &C[r * COUT + col0 + tx * TN + 2 * j]) = acc[m][j];
    }
}

// ---------------- BN stats, stage 1 (node-level buffers) --------------------
// grid=256 blocks (256 rows each), block=256 threads. Deterministic.
__global__ void __launch_bounds__(256) stats1_k(const float* __restrict__ z,
                                                int cout,
                                                float* __restrict__ part) {
    __shared__ float sh[512];
    const int t = threadIdx.x, blk = blockIdx.x;
    const int ng  = 256 / cout;
    const int ch  = t & (cout - 1);
    const int grp = t / cout;
    const int row0 = blk * 256;
    float s = 0.f, s2 = 0.f;
    for (int r = grp; r < 256; r += ng) {
        float v = z[(row0 + r) * cout + ch];
        s += v; s2 += v * v;
    }
    sh[t] = s; sh[256 + t] = s2;
    __syncthreads();
    if (t < cout) {
        float a = 0.f, b = 0.f;
        for (int g = 0; g < ng; g++) { a += sh[g * cout + t]; b += sh[256 + g * cout + t]; }
        part[blk * cout * 2 + t]        = a;
        part[blk * cout * 2 + cout + t] = b;
    }
}

// ---------------- BN stats, stage 2: sum partials -> scale/shift ------------
__global__ void stats2_k(const float* __restrict__ part,
                         const float* __restrict__ gam,
                         const float* __restrict__ bet,
                         int cout, float invM,
                         float* __restrict__ scale, float* __restrict__ shift) {
    int t = threadIdx.x;
    if (t >= cout) return;
    float s = 0.f, s2 = 0.f;
    for (int blk = 0; blk < 256; blk++) {
        s  += part[blk * cout * 2 + t];
        s2 += part[blk * cout * 2 + cout + t];
    }
    float m = s * invM;
    float v = fmaxf(s2 * invM - m * m, 0.f);
    float sc = gam[t] * rsqrtf(v + 1e-5f);
    scale[t] = sc;
    shift[t] = bet[t] - m * sc;
}

// ---------------- edge-level stats for layer-0 branch b ---------------------
// d_e = zb[nbr_e] - zb[ctr_e] over 524288 edges, 32 channels.
__global__ void __launch_bounds__(256) estats1_k(const float* __restrict__ zb,
                                                 const int* __restrict__ ei,
                                                 float* __restrict__ part) {
    __shared__ float sh[512];
    const int t = threadIdx.x, blk = blockIdx.x;
    const int ch = t & 31, grp = t >> 5;   // 8 groups of one warp each
    const int e0 = blk * 2048;
    float s = 0.f, s2 = 0.f;
    for (int i = grp; i < 2048; i += 8) {
        int ge  = e0 + i;
        int b   = ge >> 17;               // /EPB
        int e   = ge & (EPB - 1);
        int ctr = (b << 14) + (e >> 3);   // centers = repeat(arange(N),K)
        int nbr = (b << 14) + ei[b * 2 * EPB + EPB + e];
        float d = zb[nbr * 32 + ch] - zb[ctr * 32 + ch];
        s += d; s2 += d * d;
    }
    sh[t] = s; sh[256 + t] = s2;
    __syncthreads();
    if (t < 32) {
        float a = 0.f, b2 = 0.f;
        for (int g = 0; g < 8; g++) { a += sh[g * 32 + t]; b2 += sh[256 + g * 32 + t]; }
        part[blk * 64 + t]      = a;
        part[blk * 64 + 32 + t] = b2;
    }
}

// ---------------- combine: x_out = act_a(za) + max_k act_b(zb[nbr_k](-zb)) --
__global__ void __launch_bounds__(256) combine_k(const float* __restrict__ za,
                                                 const float* __restrict__ zb,
                                                 const int* __restrict__ ei,
                                                 float* __restrict__ xo,
                                                 int cout, int diffMode) {
    const int t = threadIdx.x;
    const int npb  = 256 / cout;
    const int node = blockIdx.x * npb + t / cout;
    const int ch   = t & (cout - 1);
    const int b = node >> 14, n = node & (NPTS - 1);
    const int* nb = ei + b * 2 * EPB + EPB + n * KNN;
    const int boff = b << 14;

    const float sb = g_sb[ch], hb = g_hb[ch];
    const float zc = diffMode ? zb[node * cout + ch] : 0.f;
    float mx = -1e30f;
#pragma unroll
    for (int k = 0; k < KNN; k++) {
        int nn = boff + nb[k];
        float v = (zb[nn * cout + ch] - zc) * sb + hb;
        v = v > 0.f ? v : 0.2f * v;
        mx = fmaxf(mx, v);
    }
    float va = za[node * cout + ch] * g_sa[ch] + g_ha[ch];
    va = va > 0.f ? va : 0.2f * va;
    xo[node * cout + ch] = va + mx;
}

// ---------------- cat projection: zc[row] = concat(x0..x3)[row] . Wcat ------
__global__ void __launch_bounds__(256) cat_k(const float* __restrict__ Wc) {
    const int warp = threadIdx.x >> 5, lane = threadIdx.x & 31;
    const int row = blockIdx.x * 8 + warp;
    float s = 0.f;
#pragma unroll
    for (int i = 0; i < 15; i++) {        // 480 / 32
        int j = lane + i * 32;
        float v;
        if (j < 32)       v = g_x0[row * 32  + j];
        else if (j < 96)  v = g_x1[row * 64  + (j - 32)];
        else if (j < 224) v = g_x2[row * 128 + (j - 96)];
        else              v = g_x3[row * 256 + (j - 224)];
        s += v * Wc[j];
    }
#pragma unroll
    for (int o = 16; o; o >>= 1) s += __shfl_xor_sync(0xffffffffu, s, o);
    if (lane == 0) g_zc[row] = s;
}

// ---------------- final: BN(1ch) + lrelu + bias -----------------------------
__global__ void final_k(const float* __restrict__ bias, float* __restrict__ out) {
    int i = blockIdx.x * 256 + threadIdx.x;
    float v = g_zc[i] * g_sa[0] + g_ha[0];
    v = v > 0.f ? v : 0.2f * v;
    out[i] = v + bias[0];
}

// ---------------- host orchestration ----------------------------------------
extern "C" void kernel_launch(void* const* d_in, const int* in_sizes, int n_in,
                              void* d_out, int out_size) {
    const float* x   = (const float*)d_in[0];
    const int*   ei  = (const int*)d_in[1];
    const float* W0a = (const float*)d_in[2];
    const float* g0a = (const float*)d_in[3];
    const float* b0a = (const float*)d_in[4];
    const float* W0b = (const float*)d_in[5];
    const float* g0b = (const float*)d_in[6];
    const float* b0b = (const float*)d_in[7];
    const float* W1a = (const float*)d_in[8];
    const float* g1a = (const float*)d_in[9];
    const float* b1a = (const float*)d_in[10];
    const float* W1b = (const float*)d_in[11];
    const float* g1b = (const float*)d_in[12];
    const float* b1b = (const float*)d_in[13];
    const float* W2a = (const float*)d_in[14];
    const float* g2a = (const float*)d_in[15];
    const float* b2a = (const float*)d_in[16];
    const float* W2b = (const float*)d_in[17];
    const float* g2b = (const float*)d_in[18];
    const float* b2b = (const float*)d_in[19];
    const float* W3a = (const float*)d_in[20];
    const float* g3a = (const float*)d_in[21];
    const float* b3a = (const float*)d_in[22];
    const float* W3b = (const float*)d_in[23];
    const float* g3b = (const float*)d_in[24];
    const float* b3b = (const float*)d_in[25];
    const float* Wct = (const float*)d_in[26];
    const float* gct = (const float*)d_in[27];
    const float* bct = (const float*)d_in[28];
    const float* bia = (const float*)d_in[29];
    float* out = (float*)d_out;

    float *x0, *x1, *x2, *x3, *za, *zb, *zc, *pa, *pb, *sa, *ha, *sb, *hb;
    cudaGetSymbolAddress((void**)&x0, g_x0);
    cudaGetSymbolAddress((void**)&x1, g_x1);
    cudaGetSymbolAddress((void**)&x2, g_x2);
    cudaGetSymbolAddress((void**)&x3, g_x3);
    cudaGetSymbolAddress((void**)&za, g_za);
    cudaGetSymbolAddress((void**)&zb, g_zb);
    cudaGetSymbolAddress((void**)&zc, g_zc);
    cudaGetSymbolAddress((void**)&pa, g_pa);
    cudaGetSymbolAddress((void**)&pb, g_pb);
    cudaGetSymbolAddress((void**)&sa, g_sa);
    cudaGetSymbolAddress((void**)&ha, g_ha);
    cudaGetSymbolAddress((void**)&sb, g_sb);
    cudaGetSymbolAddress((void**)&hb, g_hb);

    const float invN = 1.0f / 65536.0f;
    const float invE = 1.0f / 524288.0f;

    // ---- layer 0: 8 -> 32 ----
    gemm_k<8, 32><<<dim3(ROWS / 128, 1), 256>>>(x, W0a, za);
    gemm_k<8, 32><<<dim3(ROWS / 128, 1), 256>>>(x, W0b, zb);
    stats1_k<<<256, 256>>>(za, 32, pa);
    stats2_k<<<1, 256>>>(pa, g0a, b0a, 32, invN, sa, ha);
    estats1_k<<<256, 256>>>(zb, ei, pb);
    stats2_k<<<1, 256>>>(pb, g0b, b0b, 32, invE, sb, hb);
    combine_k<<<ROWS * 32 / 256, 256>>>(za, zb, ei, x0, 32, 1);

    // ---- layer 1: 32 -> 64 ----
    gemm_k<32, 64><<<dim3(ROWS / 128, 1), 256>>>(x0, W1a, za);
    gemm_k<32, 64><<<dim3(ROWS / 128, 1), 256>>>(x0, W1b, zb);
    stats1_k<<<256, 256>>>(za, 64, pa);
    stats2_k<<<1, 256>>>(pa, g1a, b1a, 64, invN, sa, ha);
    stats1_k<<<256, 256>>>(zb, 64, pb);
    stats2_k<<<1, 256>>>(pb, g1b, b1b, 64, invN, sb, hb);
    combine_k<<<ROWS * 64 / 256, 256>>>(za, zb, ei, x1, 64, 0);

    // ---- layer 2: 64 -> 128 ----
    gemm_k<64, 128><<<dim3(ROWS / 128, 1), 256>>>(x1, W2a, za);
    gemm_k<64, 128><<<dim3(ROWS / 128, 1), 256>>>(x1, W2b, zb);
    stats1_k<<<256, 256>>>(za, 128, pa);
    stats2_k<<<1, 256>>>(pa, g2a, b2a, 128, invN, sa, ha);
    stats1_k<<<256, 256>>>(zb, 128, pb);
    stats2_k<<<1, 256>>>(pb, g2b, b2b, 128, invN, sb, hb);
    combine_k<<<ROWS * 128 / 256, 256>>>(za, zb, ei, x2, 128, 0);

    // ---- layer 3: 128 -> 256 ----
    gemm_k<128, 256><<<dim3(ROWS / 128, 2), 256>>>(x2, W3a, za);
    gemm_k<128, 256><<<dim3(ROWS / 128, 2), 256>>>(x2, W3b, zb);
    stats1_k<<<256, 256>>>(za, 256, pa);
    stats2_k<<<1, 256>>>(pa, g3a, b3a, 256, invN, sa, ha);
    stats1_k<<<256, 256>>>(zb, 256, pb);
    stats2_k<<<1, 256>>>(pb, g3b, b3b, 256, invN, sb, hb);
    combine_k<<<ROWS * 256 / 256, 256>>>(za, zb, ei, x3, 256, 0);

    // ---- cat 480 -> 1, BN, lrelu, +bias ----
    cat_k<<<ROWS / 8, 256>>>(Wct);
    stats1_k<<<256, 256>>>(zc, 1, pa);
    stats2_k<<<1, 256>>>(pa, gct, bct, 1, invN, sa, ha);
    final_k<<<ROWS / 256, 256>>>(bia, out);
}

// round 6
// speedup vs baseline: 1.0068x; 1.0064x over previous
#include <cuda_runtime.h>
#include <cstdint>

// Problem constants
#define ROWS  65536      // B*N rows
#define NPTS  16384      // N
#define EPB   131072     // E per batch (N*K)
#define KNN   8

// ---------------- scratch (device globals; no allocation allowed) ----------
__device__ float g_x0[ROWS * 32];
__device__ float g_x1[ROWS * 64];
__device__ float g_x2[ROWS * 128];
__device__ float g_x3[ROWS * 256];
__device__ float g_za[ROWS * 256];
__device__ float g_zb[ROWS * 256];
__device__ float g_zc[ROWS];
__device__ float g_pa[256 * 256 * 2];   // stage-1 partials (branch a)
__device__ float g_pb[256 * 256 * 2];   // stage-1 partials (branch b)
__device__ float g_sa[256], g_ha[256];  // BN scale/shift branch a
__device__ float g_sb[256], g_hb[256];  // BN scale/shift branch b

// ---------------- f32x2 helpers --------------------------------------------
__device__ __forceinline__ unsigned long long pack_dup(float a) {
    unsigned long long r;
    unsigned int ab = __float_as_uint(a);
    asm("mov.b64 %0, {%1, %1};" : "=l"(r) : "r"(ab));
    return r;
}

// ---------------- GEMM: C[ROWS,COUT] = A[ROWS,CIN] @ W[CIN,COUT] ------------
template <int CIN, int COUT>
__global__ void __launch_bounds__(256) gemm_k(const float* __restrict__ A,
                                              const float* __restrict__ W,
                                              float* __restrict__ C) {
    constexpr int BM = 128;
    constexpr int BN = (COUT < 128) ? COUT : 128;
    constexpr int TM = 8;
    constexpr int TN = BN / 16;           // 2, 4, or 8
    constexpr int BK = 8;

    __shared__ float As[BM * BK];         // [BM][BK] row-major
    __shared__ float Ws[BK * BN];         // [BK][BN]

    const int t   = threadIdx.x;
    const int tx  = t & 15;
    const int ty  = t >> 4;
    const int row0 = blockIdx.x * BM;
    const int col0 = blockIdx.y * BN;

    unsigned long long acc[TM][TN / 2];
#pragma unroll
    for (int m = 0; m < TM; m++)
#pragma unroll
        for (int j = 0; j < TN / 2; j++) acc[m][j] = 0ULL;

    for (int k0 = 0; k0 < CIN; k0 += BK) {
        // Load A tile (coalesced along K within each row)
#pragma unroll
        for (int idx = t; idx < BM * BK; idx += 256) {
            int r = idx >> 3, c = idx & 7;
            As[r * BK + c] = A[(row0 + r) * CIN + k0 + c];
        }
        // Load W tile (coalesced along COUT)
#pragma unroll
        for (int idx = t; idx < BK * BN; idx += 256) {
            int kr = idx / BN, c = idx % BN;
            Ws[kr * BN + c] = W[(k0 + kr) * COUT + col0 + c];
        }
        __syncthreads();

#pragma unroll
        for (int k = 0; k < BK; k++) {
            unsigned long long a2[TM];
#pragma unroll
            for (int m = 0; m < TM; m++)
                a2[m] = pack_dup(As[(ty * TM + m) * BK + k]);
            unsigned long long w2[TN / 2];
#pragma unroll
            for (int j = 0; j < TN / 2; j++)
                w2[j] = *reinterpret_cast<const unsigned long long*>(
                    &Ws[k * BN + tx * TN + 2 * j]);
#pragma unroll
            for (int m = 0; m < TM; m++)
#pragma unroll
                for (int j = 0; j < TN / 2; j++)
                    asm("fma.rn.f32x2 %0, %1, %2, %0;"
                        : "+l"(acc[m][j]) : "l"(a2[m]), "l"(w2[j]));
        }
        __syncthreads();
    }

#pragma unroll
    for (int m = 0; m < TM; m++) {
        int r = row0 + ty * TM + m;
#pragma unroll
        for (int j = 0; j < TN / 2; j++)
            *reinterpret_cast<unsigned long long*>(
                &C[r * COUT + col0 + tx * TN + 2 * j]) = acc[m][j];
    }
}

// ---------------- BN stats, stage 1 (node-level buffers) --------------------
// grid=256 blocks (256 rows each), block=256 threads. Deterministic.
__global__ void __launch_bounds__(256) stats1_k(const float* __restrict__ z,
                                                int cout,
                                                float* __restrict__ part) {
    __shared__ float sh[512];
    const int t = threadIdx.x, blk = blockIdx.x;
    const int ng  = 256 / cout;
    const int ch  = t & (cout - 1);
    const int grp = t / cout;
    const int row0 = blk * 256;
    float s = 0.f, s2 = 0.f;
    for (int r = grp; r < 256; r += ng) {
        float v = z[(row0 + r) * cout + ch];
        s += v; s2 += v * v;
    }
    sh[t] = s; sh[256 + t] = s2;
    __syncthreads();
    if (t < cout) {
        float a = 0.f, b = 0.f;
        for (int g = 0; g < ng; g++) { a += sh[g * cout + t]; b += sh[256 + g * cout + t]; }
        part[blk * cout * 2 + t]        = a;
        part[blk * cout * 2 + cout + t] = b;
    }
}

// ---------------- BN stats, stage 2: sum partials -> scale/shift ------------
__global__ void stats2_k(const float* __restrict__ part,
                         const float* __restrict__ gam,
                         const float* __restrict__ bet,
                         int cout, float invM,
                         float* __restrict__ scale, float* __restrict__ shift) {
    int t = threadIdx.x;
    if (t >= cout) return;
    float s = 0.f, s2 = 0.f;
    for (int blk = 0; blk < 256; blk++) {
        s  += part[blk * cout * 2 + t];
        s2 += part[blk * cout * 2 + cout + t];
    }
    float m = s * invM;
    float v = fmaxf(s2 * invM - m * m, 0.f);
    float sc = gam[t] * rsqrtf(v + 1e-5f);
    scale[t] = sc;
    shift[t] = bet[t] - m * sc;
}

// ---------------- edge-level stats for layer-0 branch b ---------------------
// d_e = zb[nbr_e] - zb[ctr_e] over 524288 edges, 32 channels.
__global__ void __launch_bounds__(256) estats1_k(const float* __restrict__ zb,
                                                 const int* __restrict__ ei,
                                                 float* __restrict__ part) {
    __shared__ float sh[512];
    const int t = threadIdx.x, blk = blockIdx.x;
    const int ch = t & 31, grp = t >> 5;   // 8 groups of one warp each
    const int e0 = blk * 2048;
    float s = 0.f, s2 = 0.f;
    for (int i = grp; i < 2048; i += 8) {
        int ge  = e0 + i;
        int b   = ge >> 17;               // /EPB
        int e   = ge & (EPB - 1);
        int ctr = (b << 14) + (e >> 3);   // centers = repeat(arange(N),K)
        int nbr = (b << 14) + ei[b * 2 * EPB + EPB + e];
        float d = zb[nbr * 32 + ch] - zb[ctr * 32 + ch];
        s += d; s2 += d * d;
    }
    sh[t] = s; sh[256 + t] = s2;
    __syncthreads();
    if (t < 32) {
        float a = 0.f, b2 = 0.f;
        for (int g = 0; g < 8; g++) { a += sh[g * 32 + t]; b2 += sh[256 + g * 32 + t]; }
        part[blk * 64 + t]      = a;
        part[blk * 64 + 32 + t] = b2;
    }
}

// ---------------- combine: x_out = act_a(za) + max_k act_b(zb[nbr_k](-zb)) --
__global__ void __launch_bounds__(256) combine_k(const float* __restrict__ za,
                                                 const float* __restrict__ zb,
                                                 const int* __restrict__ ei,
                                                 float* __restrict__ xo,
                                                 int cout, int diffMode) {
    const int t = threadIdx.x;
    const int npb  = 256 / cout;
    const int node = blockIdx.x * npb + t / cout;
    const int ch   = t & (cout - 1);
    const int b = node >> 14, n = node & (NPTS - 1);
    const int* nb = ei + b * 2 * EPB + EPB + n * KNN;
    const int boff = b << 14;

    const float sb = g_sb[ch], hb = g_hb[ch];
    const float zc = diffMode ? zb[node * cout + ch] : 0.f;
    float mx = -1e30f;
#pragma unroll
    for (int k = 0; k < KNN; k++) {
        int nn = boff + nb[k];
        float v = (zb[nn * cout + ch] - zc) * sb + hb;
        v = v > 0.f ? v : 0.2f * v;
        mx = fmaxf(mx, v);
    }
    float va = za[node * cout + ch] * g_sa[ch] + g_ha[ch];
    va = va > 0.f ? va : 0.2f * va;
    xo[node * cout + ch] = va + mx;
}

// ---------------- cat projection: zc[row] = concat(x0..x3)[row] . Wcat ------
__global__ void __launch_bounds__(256) cat_k(const float* __restrict__ Wc) {
    const int warp = threadIdx.x >> 5, lane = threadIdx.x & 31;
    const int row = blockIdx.x * 8 + warp;
    float s = 0.f;
#pragma unroll
    for (int i = 0; i < 15; i++) {        // 480 / 32
        int j = lane + i * 32;
        float v;
        if (j < 32)       v = g_x0[row * 32  + j];
        else if (j < 96)  v = g_x1[row * 64  + (j - 32)];
        else if (j < 224) v = g_x2[row * 128 + (j - 96)];
        else              v = g_x3[row * 256 + (j - 224)];
        s += v * Wc[j];
    }
#pragma unroll
    for (int o = 16; o; o >>= 1) s += __shfl_xor_sync(0xffffffffu, s, o);
    if (lane == 0) g_zc[row] = s;
}

// ---------------- final: BN(1ch) + lrelu + bias -----------------------------
__global__ void final_k(const float* __restrict__ bias, float* __restrict__ out) {
    int i = blockIdx.x * 256 + threadIdx.x;
    float v = g_zc[i] * g_sa[0] + g_ha[0];
    v = v > 0.f ? v : 0.2f * v;
    out[i] = v + bias[0];
}

// ---------------- host orchestration ----------------------------------------
extern "C" void kernel_launch(void* const* d_in, const int* in_sizes, int n_in,
                              void* d_out, int out_size) {
    const float* x   = (const float*)d_in[0];
    const int*   ei  = (const int*)d_in[1];
    const float* W0a = (const float*)d_in[2];
    const float* g0a = (const float*)d_in[3];
    const float* b0a = (const float*)d_in[4];
    const float* W0b = (const float*)d_in[5];
    const float* g0b = (const float*)d_in[6];
    const float* b0b = (const float*)d_in[7];
    const float* W1a = (const float*)d_in[8];
    const float* g1a = (const float*)d_in[9];
    const float* b1a = (const float*)d_in[10];
    const float* W1b = (const float*)d_in[11];
    const float* g1b = (const float*)d_in[12];
    const float* b1b = (const float*)d_in[13];
    const float* W2a = (const float*)d_in[14];
    const float* g2a = (const float*)d_in[15];
    const float* b2a = (const float*)d_in[16];
    const float* W2b = (const float*)d_in[17];
    const float* g2b = (const float*)d_in[18];
    const float* b2b = (const float*)d_in[19];
    const float* W3a = (const float*)d_in[20];
    const float* g3a = (const float*)d_in[21];
    const float* b3a = (const float*)d_in[22];
    const float* W3b = (const float*)d_in[23];
    const float* g3b = (const float*)d_in[24];
    const float* b3b = (const float*)d_in[25];
    const float* Wct = (const float*)d_in[26];
    const float* gct = (const float*)d_in[27];
    const float* bct = (const float*)d_in[28];
    const float* bia = (const float*)d_in[29];
    float* out = (float*)d_out;

    float *x0, *x1, *x2, *x3, *za, *zb, *zc, *pa, *pb, *sa, *ha, *sb, *hb;
    cudaGetSymbolAddress((void**)&x0, g_x0);
    cudaGetSymbolAddress((void**)&x1, g_x1);
    cudaGetSymbolAddress((void**)&x2, g_x2);
    cudaGetSymbolAddress((void**)&x3, g_x3);
    cudaGetSymbolAddress((void**)&za, g_za);
    cudaGetSymbolAddress((void**)&zb, g_zb);
    cudaGetSymbolAddress((void**)&zc, g_zc);
    cudaGetSymbolAddress((void**)&pa, g_pa);
    cudaGetSymbolAddress((void**)&pb, g_pb);
    cudaGetSymbolAddress((void**)&sa, g_sa);
    cudaGetSymbolAddress((void**)&ha, g_ha);
    cudaGetSymbolAddress((void**)&sb, g_sb);
    cudaGetSymbolAddress((void**)&hb, g_hb);

    const float invN = 1.0f / 65536.0f;
    const float invE = 1.0f / 524288.0f;

    // ---- layer 0: 8 -> 32 ----
    gemm_k<8, 32><<<dim3(ROWS / 128, 1), 256>>>(x, W0a, za);
    gemm_k<8, 32><<<dim3(ROWS / 128, 1), 256>>>(x, W0b, zb);
    stats1_k<<<256, 256>>>(za, 32, pa);
    stats2_k<<<1, 256>>>(pa, g0a, b0a, 32, invN, sa, ha);
    estats1_k<<<256, 256>>>(zb, ei, pb);
    stats2_k<<<1, 256>>>(pb, g0b, b0b, 32, invE, sb, hb);
    combine_k<<<ROWS * 32 / 256, 256>>>(za, zb, ei, x0, 32, 1);

    // ---- layer 1: 32 -> 64 ----
    gemm_k<32, 64><<<dim3(ROWS / 128, 1), 256>>>(x0, W1a, za);
    gemm_k<32, 64><<<dim3(ROWS / 128, 1), 256>>>(x0, W1b, zb);
    stats1_k<<<256, 256>>>(za, 64, pa);
    stats2_k<<<1, 256>>>(pa, g1a, b1a, 64, invN, sa, ha);
    stats1_k<<<256, 256>>>(zb, 64, pb);
    stats2_k<<<1, 256>>>(pb, g1b, b1b, 64, invN, sb, hb);
    combine_k<<<ROWS * 64 / 256, 256>>>(za, zb, ei, x1, 64, 0);

    // ---- layer 2: 64 -> 128 ----
    gemm_k<64, 128><<<dim3(ROWS / 128, 1), 256>>>(x1, W2a, za);
    gemm_k<64, 128><<<dim3(ROWS / 128, 1), 256>>>(x1, W2b, zb);
    stats1_k<<<256, 256>>>(za, 128, pa);
    stats2_k<<<1, 256>>>(pa, g2a, b2a, 128, invN, sa, ha);
    stats1_k<<<256, 256>>>(zb, 128, pb);
    stats2_k<<<1, 256>>>(pb, g2b, b2b, 128, invN, sb, hb);
    combine_k<<<ROWS * 128 / 256, 256>>>(za, zb, ei, x2, 128, 0);

    // ---- layer 3: 128 -> 256 ----
    gemm_k<128, 256><<<dim3(ROWS / 128, 2), 256>>>(x2, W3a, za);
    gemm_k<128, 256><<<dim3(ROWS / 128, 2), 256>>>(x2, W3b, zb);
    stats1_k<<<256, 256>>>(za, 256, pa);
    stats2_k<<<1, 256>>>(pa, g3a, b3a, 256, invN, sa, ha);
    stats1_k<<<256, 256>>>(zb, 256, pb);
    stats2_k<<<1, 256>>>(pb, g3b, b3b, 256, invN, sb, hb);
    combine_k<<<ROWS * 256 / 256, 256>>>(za, zb, ei, x3, 256, 0);

    // ---- cat 480 -> 1, BN, lrelu, +bias ----
    cat_k<<<ROWS / 8, 256>>>(Wct);
    stats1_k<<<256, 256>>>(zc, 1, pa);
    stats2_k<<<1, 256>>>(pa, gct, bct, 1, invN, sa, ha);
    final_k<<<ROWS / 256, 256>>>(bia, out);
}

// round 7
// speedup vs baseline: 1.4144x; 1.4048x over previous
#include <cuda_runtime.h>
#include <cstdint>

// Problem constants
#define ROWS  65536      // B*N rows
#define NPTS  16384      // N
#define EPB   131072     // E per batch (N*K)
#define KNN   8
#define GRIDX 512        // ROWS / 128 row-blocks per GEMM

// ---------------- scratch (device globals; no allocation allowed) ----------
__device__ float g_x0[ROWS * 32];
__device__ float g_x1[ROWS * 64];
__device__ float g_x2[ROWS * 128];
__device__ float g_x3[ROWS * 256];
__device__ float g_za[ROWS * 256];
__device__ float g_zb[ROWS * 256];
__device__ float g_zc[ROWS];
__device__ float g_pa[256 * GRIDX * 2];   // stat partials (branch a): [ch*GRIDX+blk], sumsq at +COUT*GRIDX
__device__ float g_pb[256 * GRIDX * 2];   // stat partials (branch b)
__device__ float g_sa[256], g_ha[256];    // BN scale/shift branch a
__device__ float g_sb[256], g_hb[256];    // BN scale/shift branch b

// ---------------- f32x2 helpers --------------------------------------------
__device__ __forceinline__ unsigned long long pack_dup(float a) {
    unsigned long long r;
    unsigned int ab = __float_as_uint(a);
    asm("mov.b64 %0, {%1, %1};" : "=l"(r) : "r"(ab));
    return r;
}
__device__ __forceinline__ float f2lo(unsigned long long v) {
    return __uint_as_float((unsigned int)(v & 0xffffffffULL));
}
__device__ __forceinline__ float f2hi(unsigned long long v) {
    return __uint_as_float((unsigned int)(v >> 32));
}

// ---------------- GEMM: C[ROWS,COUT] = A[ROWS,CIN] @ W[CIN,COUT] ------------
// Thread (tx,ty): rows ty*8..+7, column pairs {tx*2 + 32*j} -> conflict-free
// LDS.64 on Ws (16 lanes x stride 2 floats covers all 32 banks once).
// STATS: fused per-block column sum/sumsq partials -> part.
template <int CIN, int COUT, bool STATS>
__global__ void __launch_bounds__(256) gemm_k(const float* __restrict__ A,
                                              const float* __restrict__ W,
                                              float* __restrict__ C,
                                              float* __restrict__ part) {
    constexpr int BM = 128;
    constexpr int BN = (COUT < 128) ? COUT : 128;
    constexpr int TM = 8;
    constexpr int TN = BN / 16;           // 2, 4, or 8
    constexpr int NJ = TN / 2;            // column pairs per thread
    constexpr int BK = 8;

    __shared__ float sh[BM * BK + BK * BN];   // As | Ws ; reused for stat reduce
    float* As = sh;                            // [BM][BK]
    float* Ws = sh + BM * BK;                  // [BK][BN]

    const int t   = threadIdx.x;
    const int tx  = t & 15;
    const int ty  = t >> 4;
    const int row0 = blockIdx.x * BM;
    const int col0 = blockIdx.y * BN;

    unsigned long long acc[TM][NJ];
#pragma unroll
    for (int m = 0; m < TM; m++)
#pragma unroll
        for (int j = 0; j < NJ; j++) acc[m][j] = 0ULL;

    for (int k0 = 0; k0 < CIN; k0 += BK) {
#pragma unroll
        for (int idx = t; idx < BM * BK; idx += 256) {
            int r = idx >> 3, c = idx & 7;
            As[r * BK + c] = A[(row0 + r) * CIN + k0 + c];
        }
#pragma unroll
        for (int idx = t; idx < BK * BN; idx += 256) {
            int kr = idx / BN, c = idx % BN;
            Ws[kr * BN + c] = W[(k0 + kr) * COUT + col0 + c];
        }
        __syncthreads();

#pragma unroll
        for (int k = 0; k < BK; k++) {
            unsigned long long a2[TM];
#pragma unroll
            for (int m = 0; m < TM; m++)
                a2[m] = pack_dup(As[(ty * TM + m) * BK + k]);
            unsigned long long w2[NJ];
#pragma unroll
            for (int j = 0; j < NJ; j++)
                w2[j] = *reinterpret_cast<const unsigned long long*>(
                    &Ws[k * BN + tx * 2 + 32 * j]);
#pragma unroll
            for (int m = 0; m < TM; m++)
#pragma unroll
                for (int j = 0; j < NJ; j++)
                    asm("fma.rn.f32x2 %0, %1, %2, %0;"
                        : "+l"(acc[m][j]) : "l"(a2[m]), "l"(w2[j]));
        }
        __syncthreads();
    }

    // Store C
#pragma unroll
    for (int m = 0; m < TM; m++) {
        int r = row0 + ty * TM + m;
#pragma unroll
        for (int j = 0; j < NJ; j++)
            *reinterpret_cast<unsigned long long*>(
                &C[r * COUT + col0 + tx * 2 + 32 * j]) = acc[m][j];
    }

    if (STATS) {
        float* red = sh;   // 16 * BN floats (fits: BM*BK = 1024 >= 16*BN/2... total sh >= 16*BN)
        // ---- pass 1: column sums ----
#pragma unroll
        for (int j = 0; j < NJ; j++) {
            float s0 = 0.f, s1 = 0.f;
#pragma unroll
            for (int m = 0; m < TM; m++) { s0 += f2lo(acc[m][j]); s1 += f2hi(acc[m][j]); }
            red[ty * BN + tx * 2 + 32 * j]     = s0;
            red[ty * BN + tx * 2 + 32 * j + 1] = s1;
        }
        __syncthreads();
        if (t < BN) {
            float s = 0.f;
#pragma unroll
            for (int g = 0; g < 16; g++) s += red[g * BN + t];
            part[(col0 + t) * GRIDX + blockIdx.x] = s;
        }
        __syncthreads();
        // ---- pass 2: column sums of squares ----
#pragma unroll
        for (int j = 0; j < NJ; j++) {
            float s0 = 0.f, s1 = 0.f;
#pragma unroll
            for (int m = 0; m < TM; m++) {
                float lo = f2lo(acc[m][j]), hi = f2hi(acc[m][j]);
                s0 += lo * lo; s1 += hi * hi;
            }
            red[ty * BN + tx * 2 + 32 * j]     = s0;
            red[ty * BN + tx * 2 + 32 * j + 1] = s1;
        }
        __syncthreads();
        if (t < BN) {
            float s = 0.f;
#pragma unroll
            for (int g = 0; g < 16; g++) s += red[g * BN + t];
            part[COUT * GRIDX + (col0 + t) * GRIDX + blockIdx.x] = s;
        }
    }
}

// ---------------- BN stats stage 2 (parallel): one block per channel --------
__global__ void __launch_bounds__(256) stats2p_k(const float* __restrict__ part,
                                                 const float* __restrict__ gam,
                                                 const float* __restrict__ bet,
                                                 int cout, int nblk, float invM,
                                                 float* __restrict__ scale,
                                                 float* __restrict__ shift) {
    const int ch = blockIdx.x, t = threadIdx.x;
    const float* ps = part + (size_t)ch * nblk;
    const float* pq = part + (size_t)cout * nblk + (size_t)ch * nblk;
    float s = 0.f, s2 = 0.f;
    for (int i = t; i < nblk; i += 256) { s += ps[i]; s2 += pq[i]; }
#pragma unroll
    for (int o = 16; o; o >>= 1) {
        s  += __shfl_xor_sync(0xffffffffu, s, o);
        s2 += __shfl_xor_sync(0xffffffffu, s2, o);
    }
    __shared__ float sw[16];
    int w = t >> 5, l = t & 31;
    if (l == 0) { sw[w] = s; sw[8 + w] = s2; }
    __syncthreads();
    if (t == 0) {
        float a = 0.f, b = 0.f;
#pragma unroll
        for (int g = 0; g < 8; g++) { a += sw[g]; b += sw[8 + g]; }
        float m = a * invM;
        float v = fmaxf(b * invM - m * m, 0.f);
        float sc = gam[ch] * rsqrtf(v + 1e-5f);
        scale[ch] = sc;
        shift[ch] = bet[ch] - m * sc;
    }
}

// ---------------- edge-level stats for layer-0 branch b ---------------------
// d_e = zb[nbr_e] - zb[ctr_e] over 524288 edges, 32 channels.
// partial layout: part[ch*256 + blk], sumsq at part[32*256 + ch*256 + blk]
__global__ void __launch_bounds__(256) estats1_k(const float* __restrict__ zb,
                                                 const int* __restrict__ ei,
                                                 float* __restrict__ part) {
    __shared__ float sh[512];
    const int t = threadIdx.x, blk = blockIdx.x;
    const int ch = t & 31, grp = t >> 5;   // 8 warps
    const int e0 = blk * 2048;
    float s = 0.f, s2 = 0.f;
    for (int i = grp; i < 2048; i += 8) {
        int ge  = e0 + i;
        int b   = ge >> 17;
        int e   = ge & (EPB - 1);
        int ctr = (b << 14) + (e >> 3);
        int nbr = (b << 14) + ei[b * 2 * EPB + EPB + e];
        float d = zb[nbr * 32 + ch] - zb[ctr * 32 + ch];
        s += d; s2 += d * d;
    }
    sh[t] = s; sh[256 + t] = s2;
    __syncthreads();
    if (t < 32) {
        float a = 0.f, b2 = 0.f;
#pragma unroll
        for (int g = 0; g < 8; g++) { a += sh[g * 32 + t]; b2 += sh[256 + g * 32 + t]; }
        part[t * 256 + blk]            = a;
        part[32 * 256 + t * 256 + blk] = b2;
    }
}

// ---------------- combine: x_out = act_a(za) + max_k act_b(zb[nbr_k](-zb)) --
__global__ void __launch_bounds__(256) combine_k(const float* __restrict__ za,
                                                 const float* __restrict__ zb,
                                                 const int* __restrict__ ei,
                                                 float* __restrict__ xo,
                                                 int cout, int diffMode) {
    const int t = threadIdx.x;
    const int npb  = 256 / cout;
    const int node = blockIdx.x * npb + t / cout;
    const int ch   = t & (cout - 1);
    const int b = node >> 14, n = node & (NPTS - 1);
    const int* nb = ei + b * 2 * EPB + EPB + n * KNN;
    const int boff = b << 14;

    const float sb = g_sb[ch], hb = g_hb[ch];
    const float zc = diffMode ? zb[node * cout + ch] : 0.f;
    float mx = -1e30f;
#pragma unroll
    for (int k = 0; k < KNN; k++) {
        int nn = boff + nb[k];
        float v = (zb[nn * cout + ch] - zc) * sb + hb;
        v = v > 0.f ? v : 0.2f * v;
        mx = fmaxf(mx, v);
    }
    float va = za[node * cout + ch] * g_sa[ch] + g_ha[ch];
    va = va > 0.f ? va : 0.2f * va;
    xo[node * cout + ch] = va + mx;
}

// ---------------- cat projection: zc[row] = concat(x0..x3)[row] . Wcat ------
// Also emits per-block stat partials: part[blk] (sum), part[8192+blk] (sumsq).
__global__ void __launch_bounds__(256) cat_k(const float* __restrict__ Wc,
                                             float* __restrict__ part) {
    __shared__ float sw[16];
    const int warp = threadIdx.x >> 5, lane = threadIdx.x & 31;
    const int row = blockIdx.x * 8 + warp;
    float s = 0.f;
#pragma unroll
    for (int i = 0; i < 15; i++) {        // 480 / 32
        int j = lane + i * 32;
        float v;
        if (j < 32)       v = g_x0[row * 32  + j];
        else if (j < 96)  v = g_x1[row * 64  + (j - 32)];
        else if (j < 224) v = g_x2[row * 128 + (j - 96)];
        else              v = g_x3[row * 256 + (j - 224)];
        s += v * Wc[j];
    }
#pragma unroll
    for (int o = 16; o; o >>= 1) s += __shfl_xor_sync(0xffffffffu, s, o);
    if (lane == 0) {
        g_zc[row] = s;
        sw[warp] = s;
        sw[8 + warp] = s * s;
    }
    __syncthreads();
    if (threadIdx.x == 0) {
        float a = 0.f, b = 0.f;
#pragma unroll
        for (int g = 0; g < 8; g++) { a += sw[g]; b += sw[8 + g]; }
        part[blockIdx.x]        = a;
        part[8192 + blockIdx.x] = b;
    }
}

// ---------------- final: BN(1ch) + lrelu + bias -----------------------------
__global__ void final_k(const float* __restrict__ bias, float* __restrict__ out) {
    int i = blockIdx.x * 256 + threadIdx.x;
    float v = g_zc[i] * g_sa[0] + g_ha[0];
    v = v > 0.f ? v : 0.2f * v;
    out[i] = v + bias[0];
}

// ---------------- host orchestration ----------------------------------------
extern "C" void kernel_launch(void* const* d_in, const int* in_sizes, int n_in,
                              void* d_out, int out_size) {
    const float* x   = (const float*)d_in[0];
    const int*   ei  = (const int*)d_in[1];
    const float* W0a = (const float*)d_in[2];
    const float* g0a = (const float*)d_in[3];
    const float* b0a = (const float*)d_in[4];
    const float* W0b = (const float*)d_in[5];
    const float* g0b = (const float*)d_in[6];
    const float* b0b = (const float*)d_in[7];
    const float* W1a = (const float*)d_in[8];
    const float* g1a = (const float*)d_in[9];
    const float* b1a = (const float*)d_in[10];
    const float* W1b = (const float*)d_in[11];
    const float* g1b = (const float*)d_in[12];
    const float* b1b = (const float*)d_in[13];
    const float* W2a = (const float*)d_in[14];
    const float* g2a = (const float*)d_in[15];
    const float* b2a = (const float*)d_in[16];
    const float* W2b = (const float*)d_in[17];
    const float* g2b = (const float*)d_in[18];
    const float* b2b = (const float*)d_in[19];
    const float* W3a = (const float*)d_in[20];
    const float* g3a = (const float*)d_in[21];
    const float* b3a = (const float*)d_in[22];
    const float* W3b = (const float*)d_in[23];
    const float* g3b = (const float*)d_in[24];
    const float* b3b = (const float*)d_in[25];
    const float* Wct = (const float*)d_in[26];
    const float* gct = (const float*)d_in[27];
    const float* bct = (const float*)d_in[28];
    const float* bia = (const float*)d_in[29];
    float* out = (float*)d_out;

    float *x0, *x1, *x2, *x3, *za, *zb, *zc, *pa, *pb, *sa, *ha, *sb, *hb;
    cudaGetSymbolAddress((void**)&x0, g_x0);
    cudaGetSymbolAddress((void**)&x1, g_x1);
    cudaGetSymbolAddress((void**)&x2, g_x2);
    cudaGetSymbolAddress((void**)&x3, g_x3);
    cudaGetSymbolAddress((void**)&za, g_za);
    cudaGetSymbolAddress((void**)&zb, g_zb);
    cudaGetSymbolAddress((void**)&zc, g_zc);
    cudaGetSymbolAddress((void**)&pa, g_pa);
    cudaGetSymbolAddress((void**)&pb, g_pb);
    cudaGetSymbolAddress((void**)&sa, g_sa);
    cudaGetSymbolAddress((void**)&ha, g_ha);
    cudaGetSymbolAddress((void**)&sb, g_sb);
    cudaGetSymbolAddress((void**)&hb, g_hb);

    const float invN = 1.0f / 65536.0f;
    const float invE = 1.0f / 524288.0f;

    // ---- layer 0: 8 -> 32 ----
    gemm_k<8, 32, true ><<<dim3(GRIDX, 1), 256>>>(x, W0a, za, pa);
    gemm_k<8, 32, false><<<dim3(GRIDX, 1), 256>>>(x, W0b, zb, nullptr);
    stats2p_k<<<32, 256>>>(pa, g0a, b0a, 32, GRIDX, invN, sa, ha);
    estats1_k<<<256, 256>>>(zb, ei, pb);
    stats2p_k<<<32, 256>>>(pb, g0b, b0b, 32, 256, invE, sb, hb);
    combine_k<<<ROWS * 32 / 256, 256>>>(za, zb, ei, x0, 32, 1);

    // ---- layer 1: 32 -> 64 ----
    gemm_k<32, 64, true><<<dim3(GRIDX, 1), 256>>>(x0, W1a, za, pa);
    gemm_k<32, 64, true><<<dim3(GRIDX, 1), 256>>>(x0, W1b, zb, pb);
    stats2p_k<<<64, 256>>>(pa, g1a, b1a, 64, GRIDX, invN, sa, ha);
    stats2p_k<<<64, 256>>>(pb, g1b, b1b, 64, GRIDX, invN, sb, hb);
    combine_k<<<ROWS * 64 / 256, 256>>>(za, zb, ei, x1, 64, 0);

    // ---- layer 2: 64 -> 128 ----
    gemm_k<64, 128, true><<<dim3(GRIDX, 1), 256>>>(x1, W2a, za, pa);
    gemm_k<64, 128, true><<<dim3(GRIDX, 1), 256>>>(x1, W2b, zb, pb);
    stats2p_k<<<128, 256>>>(pa, g2a, b2a, 128, GRIDX, invN, sa, ha);
    stats2p_k<<<128, 256>>>(pb, g2b, b2b, 128, GRIDX, invN, sb, hb);
    combine_k<<<ROWS * 128 / 256, 256>>>(za, zb, ei, x2, 128, 0);

    // ---- layer 3: 128 -> 256 ----
    gemm_k<128, 256, true><<<dim3(GRIDX, 2), 256>>>(x2, W3a, za, pa);
    gemm_k<128, 256, true><<<dim3(GRIDX, 2), 256>>>(x2, W3b, zb, pb);
    stats2p_k<<<256, 256>>>(pa, g3a, b3a, 256, GRIDX, invN, sa, ha);
    stats2p_k<<<256, 256>>>(pb, g3b, b3b, 256, GRIDX, invN, sb, hb);
    combine_k<<<ROWS * 256 / 256, 256>>>(za, zb, ei, x3, 256, 0);

    // ---- cat 480 -> 1, BN, lrelu, +bias ----
    cat_k<<<ROWS / 8, 256>>>(Wct, pa);
    stats2p_k<<<1, 256>>>(pa, gct, bct, 1, 8192, invN, sa, ha);
    final_k<<<ROWS / 256, 256>>>(bia, out);
}

// round 8
// speedup vs baseline: 1.4178x; 1.0024x over previous
#include <cuda_runtime.h>
#include <cstdint>

// Problem constants
#define ROWS  65536      // B*N rows
#define NPTS  16384      // N
#define EPB   131072     // E per batch (N*K)
#define KNN   8
#define GRIDX 512        // ROWS / 128 row-blocks per GEMM

// ---------------- scratch (device globals; no allocation allowed) ----------
__device__ float g_x0[ROWS * 32];
__device__ float g_x1[ROWS * 64];
__device__ float g_x2[ROWS * 128];
__device__ float g_x3[ROWS * 256];
__device__ float g_za[ROWS * 256];
__device__ float g_zb[ROWS * 256];
__device__ float g_zc[ROWS];
__device__ float g_pa[256 * GRIDX * 2];   // stat partials (branch a): [ch*GRIDX+blk], sumsq at +COUT*GRIDX
__device__ float g_pb[256 * GRIDX * 2];   // stat partials (branch b)
__device__ float g_sa[256], g_ha[256];    // BN scale/shift branch a
__device__ float g_sb[256], g_hb[256];    // BN scale/shift branch b

// ---------------- f32x2 helpers --------------------------------------------
__device__ __forceinline__ unsigned long long pack_dup(float a) {
    unsigned long long r;
    unsigned int ab = __float_as_uint(a);
    asm("mov.b64 %0, {%1, %1};" : "=l"(r) : "r"(ab));
    return r;
}
__device__ __forceinline__ float f2lo(unsigned long long v) {
    return __uint_as_float((unsigned int)(v & 0xffffffffULL));
}
__device__ __forceinline__ float f2hi(unsigned long long v) {
    return __uint_as_float((unsigned int)(v >> 32));
}

// ---------------- GEMM: C[ROWS,COUT] = A[ROWS,CIN] @ W[CIN,COUT] ------------
// Thread (tx,ty): rows ty*8..+7, column pairs {tx*2 + 32*j} -> conflict-free
// LDS.64 on Ws (16 lanes x stride 2 floats covers all 32 banks once).
// STATS: fused per-block column sum/sumsq partials -> part.
template <int CIN, int COUT, bool STATS>
__global__ void __launch_bounds__(256) gemm_k(const float* __restrict__ A,
                                              const float* __restrict__ W,
                                              float* __restrict__ C,
                                              float* __restrict__ part) {
    constexpr int BM = 128;
    constexpr int BN = (COUT < 128) ? COUT : 128;
    constexpr int TM = 8;
    constexpr int TN = BN / 16;           // 2, 4, or 8
    constexpr int NJ = TN / 2;            // column pairs per thread
    constexpr int BK = 8;

    __shared__ float sh[BM * BK + BK * BN];   // As | Ws ; reused for stat reduce
    float* As = sh;                            // [BM][BK]
    float* Ws = sh + BM * BK;                  // [BK][BN]

    const int t   = threadIdx.x;
    const int tx  = t & 15;
    const int ty  = t >> 4;
    const int row0 = blockIdx.x * BM;
    const int col0 = blockIdx.y * BN;

    unsigned long long acc[TM][NJ];
#pragma unroll
    for (int m = 0; m < TM; m++)
#pragma unroll
        for (int j = 0; j < NJ; j++) acc[m][j] = 0ULL;

    for (int k0 = 0; k0 < CIN; k0 += BK) {
#pragma unroll
        for (int idx = t; idx < BM * BK; idx += 256) {
            int r = idx >> 3, c = idx & 7;
            As[r * BK + c] = A[(row0 + r) * CIN + k0 + c];
        }
#pragma unroll
        for (int idx = t; idx < BK * BN; idx += 256) {
            int kr = idx / BN, c = idx % BN;
            Ws[kr * BN + c] = W[(k0 + kr) * COUT + col0 + c];
        }
        __syncthreads();

#pragma unroll
        for (int k = 0; k < BK; k++) {
            unsigned long long a2[TM];
#pragma unroll
            for (int m = 0; m < TM; m++)
                a2[m] = pack_dup(As[(ty * TM + m) * BK + k]);
            unsigned long long w2[NJ];
#pragma unroll
            for (int j = 0; j < NJ; j++)
                w2[j] = *reinterpret_cast<const unsigned long long*>(
                    &Ws[k * BN + tx * 2 + 32 * j]);
#pragma unroll
            for (int m = 0; m < TM; m++)
#pragma unroll
                for (int j = 0; j < NJ; j++)
                    asm("fma.rn.f32x2 %0, %1, %2, %0;"
                        : "+l"(acc[m][j]) : "l"(a2[m]), "l"(w2[j]));
        }
        __syncthreads();
    }

    // Store C
#pragma unroll
    for (int m = 0; m < TM; m++) {
        int r = row0 + ty * TM + m;
#pragma unroll
        for (int j = 0; j < NJ; j++)
            *reinterpret_cast<unsigned long long*>(
                &C[r * COUT + col0 + tx * 2 + 32 * j]) = acc[m][j];
    }

    if (STATS) {
        float* red = sh;   // 16 * BN floats (fits: BM*BK = 1024 >= 16*BN/2... total sh >= 16*BN)
        // ---- pass 1: column sums ----
#pragma unroll
        for (int j = 0; j < NJ; j++) {
            float s0 = 0.f, s1 = 0.f;
#pragma unroll
            for (int m = 0; m < TM; m++) { s0 += f2lo(acc[m][j]); s1 += f2hi(acc[m][j]); }
            red[ty * BN + tx * 2 + 32 * j]     = s0;
            red[ty * BN + tx * 2 + 32 * j + 1] = s1;
        }
        __syncthreads();
        if (t < BN) {
            float s = 0.f;
#pragma unroll
            for (int g = 0; g < 16; g++) s += red[g * BN + t];
            part[(col0 + t) * GRIDX + blockIdx.x] = s;
        }
        __syncthreads();
        // ---- pass 2: column sums of squares ----
#pragma unroll
        for (int j = 0; j < NJ; j++) {
            float s0 = 0.f, s1 = 0.f;
#pragma unroll
            for (int m = 0; m < TM; m++) {
                float lo = f2lo(acc[m][j]), hi = f2hi(acc[m][j]);
                s0 += lo * lo; s1 += hi * hi;
            }
            red[ty * BN + tx * 2 + 32 * j]     = s0;
            red[ty * BN + tx * 2 + 32 * j + 1] = s1;
        }
        __syncthreads();
        if (t < BN) {
            float s = 0.f;
#pragma unroll
            for (int g = 0; g < 16; g++) s += red[g * BN + t];
            part[COUT * GRIDX + (col0 + t) * GRIDX + blockIdx.x] = s;
        }
    }
}

// ---------------- BN stats stage 2 (parallel): one block per channel --------
__global__ void __launch_bounds__(256) stats2p_k(const float* __restrict__ part,
                                                 const float* __restrict__ gam,
                                                 const float* __restrict__ bet,
                                                 int cout, int nblk, float invM,
                                                 float* __restrict__ scale,
                                                 float* __restrict__ shift) {
    const int ch = blockIdx.x, t = threadIdx.x;
    const float* ps = part + (size_t)ch * nblk;
    const float* pq = part + (size_t)cout * nblk + (size_t)ch * nblk;
    float s = 0.f, s2 = 0.f;
    for (int i = t; i < nblk; i += 256) { s += ps[i]; s2 += pq[i]; }
#pragma unroll
    for (int o = 16; o; o >>= 1) {
        s  += __shfl_xor_sync(0xffffffffu, s, o);
        s2 += __shfl_xor_sync(0xffffffffu, s2, o);
    }
    __shared__ float sw[16];
    int w = t >> 5, l = t & 31;
    if (l == 0) { sw[w] = s; sw[8 + w] = s2; }
    __syncthreads();
    if (t == 0) {
        float a = 0.f, b = 0.f;
#pragma unroll
        for (int g = 0; g < 8; g++) { a += sw[g]; b += sw[8 + g]; }
        float m = a * invM;
        float v = fmaxf(b * invM - m * m, 0.f);
        float sc = gam[ch] * rsqrtf(v + 1e-5f);
        scale[ch] = sc;
        shift[ch] = bet[ch] - m * sc;
    }
}

// ---------------- edge-level stats for layer-0 branch b ---------------------
// d_e = zb[nbr_e] - zb[ctr_e] over 524288 edges, 32 channels.
// partial layout: part[ch*256 + blk], sumsq at part[32*256 + ch*256 + blk]
__global__ void __launch_bounds__(256) estats1_k(const float* __restrict__ zb,
                                                 const int* __restrict__ ei,
                                                 float* __restrict__ part) {
    __shared__ float sh[512];
    const int t = threadIdx.x, blk = blockIdx.x;
    const int ch = t & 31, grp = t >> 5;   // 8 warps
    const int e0 = blk * 2048;
    float s = 0.f, s2 = 0.f;
    for (int i = grp; i < 2048; i += 8) {
        int ge  = e0 + i;
        int b   = ge >> 17;
        int e   = ge & (EPB - 1);
        int ctr = (b << 14) + (e >> 3);
        int nbr = (b << 14) + ei[b * 2 * EPB + EPB + e];
        float d = zb[nbr * 32 + ch] - zb[ctr * 32 + ch];
        s += d; s2 += d * d;
    }
    sh[t] = s; sh[256 + t] = s2;
    __syncthreads();
    if (t < 32) {
        float a = 0.f, b2 = 0.f;
#pragma unroll
        for (int g = 0; g < 8; g++) { a += sh[g * 32 + t]; b2 += sh[256 + g * 32 + t]; }
        part[t * 256 + blk]            = a;
        part[32 * 256 + t * 256 + blk] = b2;
    }
}

// ---------------- combine: x_out = act_a(za) + max_k act_b(zb[nbr_k](-zb)) --
__global__ void __launch_bounds__(256) combine_k(const float* __restrict__ za,
                                                 const float* __restrict__ zb,
                                                 const int* __restrict__ ei,
                                                 float* __restrict__ xo,
                                                 int cout, int diffMode) {
    const int t = threadIdx.x;
    const int npb  = 256 / cout;
    const int node = blockIdx.x * npb + t / cout;
    const int ch   = t & (cout - 1);
    const int b = node >> 14, n = node & (NPTS - 1);
    const int* nb = ei + b * 2 * EPB + EPB + n * KNN;
    const int boff = b << 14;

    const float sb = g_sb[ch], hb = g_hb[ch];
    const float zc = diffMode ? zb[node * cout + ch] : 0.f;
    float mx = -1e30f;
#pragma unroll
    for (int k = 0; k < KNN; k++) {
        int nn = boff + nb[k];
        float v = (zb[nn * cout + ch] - zc) * sb + hb;
        v = v > 0.f ? v : 0.2f * v;
        mx = fmaxf(mx, v);
    }
    float va = za[node * cout + ch] * g_sa[ch] + g_ha[ch];
    va = va > 0.f ? va : 0.2f * va;
    xo[node * cout + ch] = va + mx;
}

// ---------------- cat projection: zc[row] = concat(x0..x3)[row] . Wcat ------
// Also emits per-block stat partials: part[blk] (sum), part[8192+blk] (sumsq).
__global__ void __launch_bounds__(256) cat_k(const float* __restrict__ Wc,
                                             float* __restrict__ part) {
    __shared__ float sw[16];
    const int warp = threadIdx.x >> 5, lane = threadIdx.x & 31;
    const int row = blockIdx.x * 8 + warp;
    float s = 0.f;
#pragma unroll
    for (int i = 0; i < 15; i++) {        // 480 / 32
        int j = lane + i * 32;
        float v;
        if (j < 32)       v = g_x0[row * 32  + j];
        else if (j < 96)  v = g_x1[row * 64  + (j - 32)];
        else if (j < 224) v = g_x2[row * 128 + (j - 96)];
        else              v = g_x3[row * 256 + (j - 224)];
        s += v * Wc[j];
    }
#pragma unroll
    for (int o = 16; o; o >>= 1) s += __shfl_xor_sync(0xffffffffu, s, o);
    if (lane == 0) {
        g_zc[row] = s;
        sw[warp] = s;
        sw[8 + warp] = s * s;
    }
    __syncthreads();
    if (threadIdx.x == 0) {
        float a = 0.f, b = 0.f;
#pragma unroll
        for (int g = 0; g < 8; g++) { a += sw[g]; b += sw[8 + g]; }
        part[blockIdx.x]        = a;
        part[8192 + blockIdx.x] = b;
    }
}

// ---------------- final: BN(1ch) + lrelu + bias -----------------------------
__global__ void final_k(const float* __restrict__ bias, float* __restrict__ out) {
    int i = blockIdx.x * 256 + threadIdx.x;
    float v = g_zc[i] * g_sa[0] + g_ha[0];
    v = v > 0.f ? v : 0.2f * v;
    out[i] = v + bias[0];
}

// ---------------- host orchestration ----------------------------------------
extern "C" void kernel_launch(void* const* d_in, const int* in_sizes, int n_in,
                              void* d_out, int out_size) {
    const float* x   = (const float*)d_in[0];
    const int*   ei  = (const int*)d_in[1];
    const float* W0a = (const float*)d_in[2];
    const float* g0a = (const float*)d_in[3];
    const float* b0a = (const float*)d_in[4];
    const float* W0b = (const float*)d_in[5];
    const float* g0b = (const float*)d_in[6];
    const float* b0b = (const float*)d_in[7];
    const float* W1a = (const float*)d_in[8];
    const float* g1a = (const float*)d_in[9];
    const float* b1a = (const float*)d_in[10];
    const float* W1b = (const float*)d_in[11];
    const float* g1b = (const float*)d_in[12];
    const float* b1b = (const float*)d_in[13];
    const float* W2a = (const float*)d_in[14];
    const float* g2a = (const float*)d_in[15];
    const float* b2a = (const float*)d_in[16];
    const float* W2b = (const float*)d_in[17];
    const float* g2b = (const float*)d_in[18];
    const float* b2b = (const float*)d_in[19];
    const float* W3a = (const float*)d_in[20];
    const float* g3a = (const float*)d_in[21];
    const float* b3a = (const float*)d_in[22];
    const float* W3b = (const float*)d_in[23];
    const float* g3b = (const float*)d_in[24];
    const float* b3b = (const float*)d_in[25];
    const float* Wct = (const float*)d_in[26];
    const float* gct = (const float*)d_in[27];
    const float* bct = (const float*)d_in[28];
    const float* bia = (const float*)d_in[29];
    float* out = (float*)d_out;

    float *x0, *x1, *x2, *x3, *za, *zb, *zc, *pa, *pb, *sa, *ha, *sb, *hb;
    cudaGetSymbolAddress((void**)&x0, g_x0);
    cudaGetSymbolAddress((void**)&x1, g_x1);
    cudaGetSymbolAddress((void**)&x2, g_x2);
    cudaGetSymbolAddress((void**)&x3, g_x3);
    cudaGetSymbolAddress((void**)&za, g_za);
    cudaGetSymbolAddress((void**)&zb, g_zb);
    cudaGetSymbolAddress((void**)&zc, g_zc);
    cudaGetSymbolAddress((void**)&pa, g_pa);
    cudaGetSymbolAddress((void**)&pb, g_pb);
    cudaGetSymbolAddress((void**)&sa, g_sa);
    cudaGetSymbolAddress((void**)&ha, g_ha);
    cudaGetSymbolAddress((void**)&sb, g_sb);
    cudaGetSymbolAddress((void**)&hb, g_hb);

    const float invN = 1.0f / 65536.0f;
    const float invE = 1.0f / 524288.0f;

    // ---- layer 0: 8 -> 32 ----
    gemm_k<8, 32, true ><<<dim3(GRIDX, 1), 256>>>(x, W0a, za, pa);
    gemm_k<8, 32, false><<<dim3(GRIDX, 1), 256>>>(x, W0b, zb, nullptr);
    stats2p_k<<<32, 256>>>(pa, g0a, b0a, 32, GRIDX, invN, sa, ha);
    estats1_k<<<256, 256>>>(zb, ei, pb);
    stats2p_k<<<32, 256>>>(pb, g0b, b0b, 32, 256, invE, sb, hb);
    combine_k<<<ROWS * 32 / 256, 256>>>(za, zb, ei, x0, 32, 1);

    // ---- layer 1: 32 -> 64 ----
    gemm_k<32, 64, true><<<dim3(GRIDX, 1), 256>>>(x0, W1a, za, pa);
    gemm_k<32, 64, true><<<dim3(GRIDX, 1), 256>>>(x0, W1b, zb, pb);
    stats2p_k<<<64, 256>>>(pa, g1a, b1a, 64, GRIDX, invN, sa, ha);
    stats2p_k<<<64, 256>>>(pb, g1b, b1b, 64, GRIDX, invN, sb, hb);
    combine_k<<<ROWS * 64 / 256, 256>>>(za, zb, ei, x1, 64, 0);

    // ---- layer 2: 64 -> 128 ----
    gemm_k<64, 128, true><<<dim3(GRIDX, 1), 256>>>(x1, W2a, za, pa);
    gemm_k<64, 128, true><<<dim3(GRIDX, 1), 256>>>(x1, W2b, zb, pb);
    stats2p_k<<<128, 256>>>(pa, g2a, b2a, 128, GRIDX, invN, sa, ha);
    stats2p_k<<<128, 256>>>(pb, g2b, b2b, 128, GRIDX, invN, sb, hb);
    combine_k<<<ROWS * 128 / 256, 256>>>(za, zb, ei, x2, 128, 0);

    // ---- layer 3: 128 -> 256 ----
    gemm_k<128, 256, true><<<dim3(GRIDX, 2), 256>>>(x2, W3a, za, pa);
    gemm_k<128, 256, true><<<dim3(GRIDX, 2), 256>>>(x2, W3b, zb, pb);
    stats2p_k<<<256, 256>>>(pa, g3a, b3a, 256, GRIDX, invN, sa, ha);
    stats2p_k<<<256, 256>>>(pb, g3b, b3b, 256, GRIDX, invN, sb, hb);
    combine_k<<<ROWS * 256 / 256, 256>>>(za, zb, ei, x3, 256, 0);

    // ---- cat 480 -> 1, BN, lrelu, +bias ----
    cat_k<<<ROWS / 8, 256>>>(Wct, pa);
    stats2p_k<<<1, 256>>>(pa, gct, bct, 1, 8192, invN, sa, ha);
    final_k<<<ROWS / 256, 256>>>(bia, out);
}